// round 1
// baseline (speedup 1.0000x reference)
#include <cuda_runtime.h>
#include <math.h>

#define NN   100000
#define EE   1600000
#define ETOT (EE + NN)
#define INC  128
#define HC   128     // HEADS*OUT_C
#define OC   32
#define HEADS 4
#define NEG_SLOPE 0.2f

// ---------------- device scratch (static: no allocations allowed) ----------
__device__ int   g_is64;
__device__ int   g_src[ETOT];
__device__ int   g_dst[ETOT];
__device__ float g_h  [NN * HC];        // projected features [N,128]
__device__ float g_as [NN * HEADS];     // per-node src logits
__device__ float g_ad [NN * HEADS];     // per-node dst logits
__device__ float g_w  [ETOT * HEADS];   // exp(leaky(e)) per edge/head
__device__ float g_sum[NN * HEADS];     // softmax denominators
__device__ float g_acc[NN * HC];        // aggregated output before final linear

// ---------------- dtype detection (int64 vs int32 edge_index) --------------
__global__ void k_detect(const void* ei) {
    if (blockIdx.x == 0 && threadIdx.x == 0) {
        const long long* p = (const long long*)ei;
        int ok = 0;
        #pragma unroll 1
        for (int i = 0; i < 64; ++i) {
            long long v = p[i];
            if (v >= 0 && v < (long long)NN) ok++;
        }
        g_is64 = (ok == 64) ? 1 : 0;
    }
}

// build int32 src/dst arrays, append self loops
__global__ void k_convert(const void* ei, int e, int n) {
    int i = blockIdx.x * blockDim.x + threadIdx.x;
    int tot = e + n;
    if (i >= tot) return;
    int s, d;
    if (i < e) {
        if (g_is64) {
            const long long* p = (const long long*)ei;
            s = (int)p[i];
            d = (int)p[e + i];
        } else {
            const int* p = (const int*)ei;
            s = p[i];
            d = p[e + i];
        }
    } else {
        s = d = i - e;
    }
    g_src[i] = s;
    g_dst[i] = d;
}

__global__ void k_zero(int n) {
    int i = blockIdx.x * blockDim.x + threadIdx.x;
    if (i < n * HC)    g_acc[i] = 0.0f;
    if (i < n * HEADS) g_sum[i] = 0.0f;
}

// ---------------- GEMM: h = x @ W^T  (W: [HC, INC] row-major) --------------
// block: 128 threads, 32 rows. W transposed in smem, padded stride 132.
__global__ void k_gemm(const float* __restrict__ x, const float* __restrict__ W, int n) {
    extern __shared__ float sm[];
    float* Ws = sm;                  // [128][132]  Ws[k*132 + j] = W[j][k]
    float* xs = sm + 128 * 132;      // [32][128]
    int tid = threadIdx.x;

    for (int idx = tid; idx < HC * INC; idx += 128) {
        int j = idx >> 7, k = idx & 127;
        Ws[k * 132 + j] = W[idx];
    }
    int row0 = blockIdx.x * 32;
    for (int idx = tid; idx < 32 * INC; idx += 128) {
        int r = idx >> 7;
        xs[idx] = (row0 + r < n) ? x[(size_t)row0 * INC + idx] : 0.0f;
    }
    __syncthreads();

    int tx = tid & 31;   // 4-col group
    int ty = tid >> 5;   // 8-row group
    float acc[8][4];
    #pragma unroll
    for (int r = 0; r < 8; ++r)
        #pragma unroll
        for (int c = 0; c < 4; ++c) acc[r][c] = 0.0f;

    #pragma unroll 4
    for (int k = 0; k < 128; ++k) {
        float4 wv = *(const float4*)&Ws[k * 132 + tx * 4];
        #pragma unroll
        for (int r = 0; r < 8; ++r) {
            float xv = xs[(ty * 8 + r) * 128 + k];
            acc[r][0] = fmaf(xv, wv.x, acc[r][0]);
            acc[r][1] = fmaf(xv, wv.y, acc[r][1]);
            acc[r][2] = fmaf(xv, wv.z, acc[r][2]);
            acc[r][3] = fmaf(xv, wv.w, acc[r][3]);
        }
    }
    #pragma unroll
    for (int r = 0; r < 8; ++r) {
        int row = row0 + ty * 8 + r;
        if (row < n)
            *(float4*)&g_h[(size_t)row * HC + tx * 4] =
                make_float4(acc[r][0], acc[r][1], acc[r][2], acc[r][3]);
    }
}

// ---------------- per-node attention logits --------------------------------
__global__ void k_logits(const float* __restrict__ att_s,
                         const float* __restrict__ att_d, int n) {
    int w    = (blockIdx.x * blockDim.x + threadIdx.x) >> 5;
    int lane = threadIdx.x & 31;
    if (w >= n) return;
    float ps[HEADS], pd[HEADS];
    #pragma unroll
    for (int hh = 0; hh < HEADS; ++hh) {
        float hv = g_h[(size_t)w * HC + hh * OC + lane];
        ps[hh] = hv * __ldg(&att_s[hh * OC + lane]);
        pd[hh] = hv * __ldg(&att_d[hh * OC + lane]);
    }
    #pragma unroll
    for (int hh = 0; hh < HEADS; ++hh) {
        #pragma unroll
        for (int o = 16; o > 0; o >>= 1) {
            ps[hh] += __shfl_xor_sync(0xffffffffu, ps[hh], o);
            pd[hh] += __shfl_xor_sync(0xffffffffu, pd[hh], o);
        }
    }
    if (lane == 0) {
        #pragma unroll
        for (int hh = 0; hh < HEADS; ++hh) {
            g_as[w * HEADS + hh] = ps[hh];
            g_ad[w * HEADS + hh] = pd[hh];
        }
    }
}

// ---------------- edge pass 1: unnormalized weights + denominators ---------
// alpha = exp(e)/sum(exp(e)) == exp(e-m)/sum(exp(e-m)); |e| small -> skip max.
__global__ void k_edge1(int etot) {
    int ed = blockIdx.x * blockDim.x + threadIdx.x;
    if (ed >= etot) return;
    int s = g_src[ed], d = g_dst[ed];
    float4 as = *(const float4*)&g_as[s * 4];
    float4 ad = *(const float4*)&g_ad[d * 4];
    float e0 = as.x + ad.x, e1 = as.y + ad.y, e2 = as.z + ad.z, e3 = as.w + ad.w;
    e0 = e0 > 0.f ? e0 : NEG_SLOPE * e0;
    e1 = e1 > 0.f ? e1 : NEG_SLOPE * e1;
    e2 = e2 > 0.f ? e2 : NEG_SLOPE * e2;
    e3 = e3 > 0.f ? e3 : NEG_SLOPE * e3;
    float w0 = expf(e0), w1 = expf(e1), w2 = expf(e2), w3 = expf(e3);
    *(float4*)&g_w[(size_t)ed * 4] = make_float4(w0, w1, w2, w3);
    atomicAdd(&g_sum[d * 4 + 0], w0);
    atomicAdd(&g_sum[d * 4 + 1], w1);
    atomicAdd(&g_sum[d * 4 + 2], w2);
    atomicAdd(&g_sum[d * 4 + 3], w3);
}

// ---------------- edge pass 2: scatter alpha * h[src] into g_acc[dst] ------
// one warp per edge; lane handles 4 contiguous channels (head = lane>>3)
__global__ void k_edge2(int etot) {
    long long t = (long long)blockIdx.x * blockDim.x + threadIdx.x;
    int ed = (int)(t >> 5);
    if (ed >= etot) return;
    int lane = (int)(t & 31);
    int s = g_src[ed], d = g_dst[ed];
    int hh = lane >> 3;
    float alpha = g_w[(size_t)ed * 4 + hh] / g_sum[d * 4 + hh];
    float4 hv = *(const float4*)&g_h[(size_t)s * HC + lane * 4];
    float* o = &g_acc[(size_t)d * HC + lane * 4];
    atomicAdd(o + 0, alpha * hv.x);
    atomicAdd(o + 1, alpha * hv.y);
    atomicAdd(o + 2, alpha * hv.z);
    atomicAdd(o + 3, alpha * hv.w);
}

// ---------------- final linear [128 -> 32] + ELU ----------------------------
__global__ void k_final(const float* __restrict__ bias,
                        const float* __restrict__ Wl,
                        const float* __restrict__ bl,
                        float* __restrict__ out, int n) {
    __shared__ float Wt[128 * 32];   // transposed: Wt[k*32 + oc]
    __shared__ float xr[8 * 128];
    int tid = threadIdx.x;
    for (int idx = tid; idx < OC * HC; idx += 256) {
        int oc = idx >> 7, k = idx & 127;
        Wt[k * 32 + oc] = Wl[idx];
    }
    int n0 = blockIdx.x * 8;
    for (int idx = tid; idx < 8 * HC; idx += 256) {
        int node = n0 + (idx >> 7);
        xr[idx] = (node < n) ? (g_acc[(size_t)node * HC + (idx & 127)] + __ldg(&bias[idx & 127]))
                             : 0.0f;
    }
    __syncthreads();

    int r = tid >> 5;
    int node = n0 + r;
    int oc = tid & 31;
    if (node >= n) return;
    float accv = 0.0f;
    #pragma unroll 4
    for (int k = 0; k < 128; ++k)
        accv = fmaf(xr[r * 128 + k], Wt[k * 32 + oc], accv);
    accv += __ldg(&bl[oc]);
    out[(size_t)node * OC + oc] = accv > 0.0f ? accv : (expf(accv) - 1.0f);
}

// ---------------- launch -----------------------------------------------------
extern "C" void kernel_launch(void* const* d_in, const int* in_sizes, int n_in,
                              void* d_out, int out_size) {
    const float* x     = (const float*)d_in[0];
    const void*  ei    = d_in[1];
    const float* W     = (const float*)d_in[2];
    const float* att_s = (const float*)d_in[3];
    const float* att_d = (const float*)d_in[4];
    const float* bias  = (const float*)d_in[5];
    const float* Wl    = (const float*)d_in[6];
    const float* bl    = (const float*)d_in[7];
    float* out = (float*)d_out;

    int n = in_sizes[0] / INC;
    int e = in_sizes[1] / 2;
    int etot = e + n;

    cudaFuncSetAttribute(k_gemm, cudaFuncAttributeMaxDynamicSharedMemorySize, 96 * 1024);

    k_detect<<<1, 32>>>(ei);
    k_convert<<<(etot + 255) / 256, 256>>>(ei, e, n);
    k_zero<<<(n * HC + 255) / 256, 256>>>(n);
    k_gemm<<<(n + 31) / 32, 128, (128 * 132 + 32 * 128) * sizeof(float)>>>(x, W, n);
    k_logits<<<(n * 32 + 255) / 256, 256>>>(att_s, att_d, n);
    k_edge1<<<(etot + 255) / 256, 256>>>(etot);
    {
        long long threads = (long long)etot * 32;
        int blocks = (int)((threads + 255) / 256);
        k_edge2<<<blocks, 256>>>(etot);
    }
    k_final<<<(n + 7) / 8, 256>>>(bias, Wl, bl, out, n);
}

// round 2
// speedup vs baseline: 2.0380x; 2.0380x over previous
#include <cuda_runtime.h>
#include <math.h>

#define NN   100000
#define EE   1600000
#define ETOT (EE + NN)
#define INC  128
#define HC   128     // HEADS*OUT_C
#define OC   32
#define HEADS 4
#define NEG_SLOPE 0.2f
#define SCAN_BLK 256

// ---------------- device scratch (static: no allocations allowed) ----------
__device__ int   g_is64;
__device__ int   g_src[ETOT];
__device__ int   g_dst[ETOT];
__device__ int   g_esrc[ETOT];          // CSR: src ids grouped by dst
__device__ int   g_deg[NN];             // in-degree per node
__device__ int   g_tmp[NN];             // block-local exclusive scan
__device__ int   g_part[1024];          // per-block partial sums
__device__ int   g_rowptr[NN];          // CSR row starts
__device__ int   g_cursor[NN];          // scatter cursors
__device__ float g_h  [NN * HC];        // projected features [N,128]
__device__ float g_as [NN * HEADS];     // per-node src logits
__device__ float g_ad [NN * HEADS];     // per-node dst logits
__device__ float g_acc[NN * HC];        // aggregated output before final linear

// ---------------- dtype detection (int64 vs int32 edge_index) --------------
__global__ void k_detect(const void* ei) {
    if (blockIdx.x == 0 && threadIdx.x == 0) {
        const long long* p = (const long long*)ei;
        int ok = 0;
        #pragma unroll 1
        for (int i = 0; i < 64; ++i) {
            long long v = p[i];
            if (v >= 0 && v < (long long)NN) ok++;
        }
        g_is64 = (ok == 64) ? 1 : 0;
    }
}

// build int32 src/dst arrays (+self loops) and histogram in-degrees
__global__ void k_prep(const void* ei, int e, int n) {
    int i = blockIdx.x * blockDim.x + threadIdx.x;
    int tot = e + n;
    if (i >= tot) return;
    int s, d;
    if (i < e) {
        if (g_is64) {
            const long long* p = (const long long*)ei;
            s = (int)p[i];
            d = (int)p[e + i];
        } else {
            const int* p = (const int*)ei;
            s = p[i];
            d = p[e + i];
        }
    } else {
        s = d = i - e;
    }
    g_src[i] = s;
    g_dst[i] = d;
    atomicAdd(&g_deg[d], 1);
}

__global__ void k_zero_deg(int n) {
    int i = blockIdx.x * blockDim.x + threadIdx.x;
    if (i < n) g_deg[i] = 0;
}

// ---------------- exact exclusive scan of g_deg -> g_rowptr ----------------
__global__ void k_scan1(int n) {
    __shared__ int sm[SCAN_BLK];
    int t = threadIdx.x;
    int i = blockIdx.x * SCAN_BLK + t;
    int v = (i < n) ? g_deg[i] : 0;
    sm[t] = v;
    __syncthreads();
    #pragma unroll
    for (int off = 1; off < SCAN_BLK; off <<= 1) {
        int u = (t >= off) ? sm[t - off] : 0;
        __syncthreads();
        sm[t] += u;
        __syncthreads();
    }
    if (i < n) g_tmp[i] = sm[t] - v;            // exclusive
    if (t == SCAN_BLK - 1) g_part[blockIdx.x] = sm[t];
}

__global__ void k_scan2(int nb) {
    __shared__ int sm[1024];
    int t = threadIdx.x;
    int v = (t < nb) ? g_part[t] : 0;
    sm[t] = v;
    __syncthreads();
    #pragma unroll
    for (int off = 1; off < 1024; off <<= 1) {
        int u = (t >= off) ? sm[t - off] : 0;
        __syncthreads();
        sm[t] += u;
        __syncthreads();
    }
    if (t < nb) g_part[t] = sm[t] - v;          // exclusive
}

__global__ void k_scan3(int n) {
    int i = blockIdx.x * blockDim.x + threadIdx.x;
    if (i >= n) return;
    int r = g_tmp[i] + g_part[i / SCAN_BLK];
    g_rowptr[i] = r;
    g_cursor[i] = r;
}

// ---------------- scatter edges into CSR ------------------------------------
__global__ void k_scatter(int etot) {
    int i = blockIdx.x * blockDim.x + threadIdx.x;
    if (i >= etot) return;
    int d = g_dst[i];
    int pos = atomicAdd(&g_cursor[d], 1);
    g_esrc[pos] = g_src[i];
}

// ---------------- GEMM: h = x @ W^T, fused attention logits ----------------
// 256 threads, 64 rows/block; W^T in smem (stride 132), x tile in smem.
__global__ void k_gemm(const float* __restrict__ x, const float* __restrict__ W,
                       const float* __restrict__ att_s, const float* __restrict__ att_d,
                       int n) {
    extern __shared__ float smx[];
    float* Ws = smx;                 // [128][132]  Ws[k*132 + j] = W[j][k]
    float* xs = smx + 128 * 132;     // [64][128]
    int tid = threadIdx.x;

    for (int idx = tid; idx < HC * INC; idx += 256) {
        int j = idx >> 7, k = idx & 127;
        Ws[k * 132 + j] = W[idx];
    }
    int row0 = blockIdx.x * 64;
    for (int idx = tid; idx < 64 * INC; idx += 256) {
        int r = idx >> 7;
        xs[idx] = (row0 + r < n) ? x[(size_t)row0 * INC + idx] : 0.0f;
    }
    __syncthreads();

    int tx = tid & 31;   // 4-col group (cols tx*4 .. tx*4+3)
    int ty = tid >> 5;   // 8-row group (rows ty*8 .. ty*8+7)
    float acc[8][4];
    #pragma unroll
    for (int r = 0; r < 8; ++r)
        #pragma unroll
        for (int c = 0; c < 4; ++c) acc[r][c] = 0.0f;

    #pragma unroll 4
    for (int k = 0; k < 128; ++k) {
        float4 wv = *(const float4*)&Ws[k * 132 + tx * 4];
        #pragma unroll
        for (int r = 0; r < 8; ++r) {
            float xv = xs[(ty * 8 + r) * 128 + k];
            acc[r][0] = fmaf(xv, wv.x, acc[r][0]);
            acc[r][1] = fmaf(xv, wv.y, acc[r][1]);
            acc[r][2] = fmaf(xv, wv.z, acc[r][2]);
            acc[r][3] = fmaf(xv, wv.w, acc[r][3]);
        }
    }

    // store h
    #pragma unroll
    for (int r = 0; r < 8; ++r) {
        int row = row0 + ty * 8 + r;
        if (row < n)
            *(float4*)&g_h[(size_t)row * HC + tx * 4] =
                make_float4(acc[r][0], acc[r][1], acc[r][2], acc[r][3]);
    }

    // fused logits: warp ty holds all 128 cols of its 8 rows.
    float4 asv = *(const float4*)&att_s[tx * 4];
    float4 adv = *(const float4*)&att_d[tx * 4];
    int head = tx >> 3;
    #pragma unroll
    for (int r = 0; r < 8; ++r) {
        float ps = acc[r][0] * asv.x + acc[r][1] * asv.y + acc[r][2] * asv.z + acc[r][3] * asv.w;
        float pd = acc[r][0] * adv.x + acc[r][1] * adv.y + acc[r][2] * adv.z + acc[r][3] * adv.w;
        #pragma unroll
        for (int o = 4; o > 0; o >>= 1) {
            ps += __shfl_xor_sync(0xffffffffu, ps, o);
            pd += __shfl_xor_sync(0xffffffffu, pd, o);
        }
        int row = row0 + ty * 8 + r;
        if ((tx & 7) == 0 && row < n) {
            g_as[row * HEADS + head] = ps;
            g_ad[row * HEADS + head] = pd;
        }
    }
}

// ---------------- fused softmax + aggregate: one warp per dst node ---------
// out[d] = (sum_e w_e * h[src_e]) / (sum_e w_e),  w_e = exp(leaky(as[s]+ad[d]))
__global__ void k_gather(int n) {
    int w    = (blockIdx.x * blockDim.x + threadIdx.x) >> 5;
    int lane = threadIdx.x & 31;
    if (w >= n) return;
    int start = g_rowptr[w];
    int deg   = g_deg[w];
    int hh    = lane >> 3;
    float adv = g_ad[w * HEADS + hh];

    float sum = 0.0f;
    float ax = 0.f, ay = 0.f, az = 0.f, aw = 0.f;
    const int* es = &g_esrc[start];

    int j = 0;
    for (; j + 2 <= deg; j += 2) {
        int s0 = es[j], s1 = es[j + 1];
        float a0 = g_as[s0 * HEADS + hh];
        float a1 = g_as[s1 * HEADS + hh];
        float4 h0 = *(const float4*)&g_h[(size_t)s0 * HC + lane * 4];
        float4 h1 = *(const float4*)&g_h[(size_t)s1 * HC + lane * 4];
        float e0 = a0 + adv; e0 = e0 > 0.f ? e0 : NEG_SLOPE * e0;
        float e1 = a1 + adv; e1 = e1 > 0.f ? e1 : NEG_SLOPE * e1;
        float w0 = __expf(e0), w1 = __expf(e1);
        sum += w0 + w1;
        ax = fmaf(w0, h0.x, fmaf(w1, h1.x, ax));
        ay = fmaf(w0, h0.y, fmaf(w1, h1.y, ay));
        az = fmaf(w0, h0.z, fmaf(w1, h1.z, az));
        aw = fmaf(w0, h0.w, fmaf(w1, h1.w, aw));
    }
    if (j < deg) {
        int s0 = es[j];
        float a0 = g_as[s0 * HEADS + hh];
        float4 h0 = *(const float4*)&g_h[(size_t)s0 * HC + lane * 4];
        float e0 = a0 + adv; e0 = e0 > 0.f ? e0 : NEG_SLOPE * e0;
        float w0 = __expf(e0);
        sum += w0;
        ax = fmaf(w0, h0.x, ax);
        ay = fmaf(w0, h0.y, ay);
        az = fmaf(w0, h0.z, az);
        aw = fmaf(w0, h0.w, aw);
    }
    float inv = 1.0f / sum;
    *(float4*)&g_acc[(size_t)w * HC + lane * 4] =
        make_float4(ax * inv, ay * inv, az * inv, aw * inv);
}

// ---------------- final linear [128 -> 32] + ELU ----------------------------
__global__ void k_final(const float* __restrict__ bias,
                        const float* __restrict__ Wl,
                        const float* __restrict__ bl,
                        float* __restrict__ out, int n) {
    __shared__ float Wt[128 * 32];   // transposed: Wt[k*32 + oc]
    __shared__ float xr[8 * 128];
    int tid = threadIdx.x;
    for (int idx = tid; idx < OC * HC; idx += 256) {
        int oc = idx >> 7, k = idx & 127;
        Wt[k * 32 + oc] = Wl[idx];
    }
    int n0 = blockIdx.x * 8;
    for (int idx = tid; idx < 8 * HC; idx += 256) {
        int node = n0 + (idx >> 7);
        xr[idx] = (node < n) ? (g_acc[(size_t)node * HC + (idx & 127)] + __ldg(&bias[idx & 127]))
                             : 0.0f;
    }
    __syncthreads();

    int r = tid >> 5;
    int node = n0 + r;
    int oc = tid & 31;
    if (node >= n) return;
    float accv = 0.0f;
    #pragma unroll 4
    for (int k = 0; k < 128; ++k)
        accv = fmaf(xr[r * 128 + k], Wt[k * 32 + oc], accv);
    accv += __ldg(&bl[oc]);
    out[(size_t)node * OC + oc] = accv > 0.0f ? accv : (expf(accv) - 1.0f);
}

// ---------------- launch -----------------------------------------------------
extern "C" void kernel_launch(void* const* d_in, const int* in_sizes, int n_in,
                              void* d_out, int out_size) {
    const float* x     = (const float*)d_in[0];
    const void*  ei    = d_in[1];
    const float* W     = (const float*)d_in[2];
    const float* att_s = (const float*)d_in[3];
    const float* att_d = (const float*)d_in[4];
    const float* bias  = (const float*)d_in[5];
    const float* Wl    = (const float*)d_in[6];
    const float* bl    = (const float*)d_in[7];
    float* out = (float*)d_out;

    int n = in_sizes[0] / INC;
    int e = in_sizes[1] / 2;
    int etot = e + n;
    int nscan = (n + SCAN_BLK - 1) / SCAN_BLK;

    static int smem_set = 0;
    if (!smem_set) {
        cudaFuncSetAttribute(k_gemm, cudaFuncAttributeMaxDynamicSharedMemorySize, 110 * 1024);
        smem_set = 1;
    }

    k_detect<<<1, 32>>>(ei);
    k_zero_deg<<<(n + 255) / 256, 256>>>(n);
    k_prep<<<(etot + 255) / 256, 256>>>(ei, e, n);
    k_scan1<<<nscan, SCAN_BLK>>>(n);
    k_scan2<<<1, 1024>>>(nscan);
    k_scan3<<<(n + 255) / 256, 256>>>(n);
    k_scatter<<<(etot + 255) / 256, 256>>>(etot);
    k_gemm<<<(n + 63) / 64, 256, (128 * 132 + 64 * 128) * sizeof(float)>>>(x, W, att_s, att_d, n);
    k_gather<<<(n * 32 + 255) / 256, 256>>>(n);
    k_final<<<(n + 7) / 8, 256>>>(bias, Wl, bl, out, n);
}

// round 3
// speedup vs baseline: 2.6937x; 1.3218x over previous
#include <cuda_runtime.h>
#include <math.h>

#define NN   100000
#define EE   1600000
#define ETOT (EE + NN)
#define INC  128
#define HC   128     // HEADS*OUT_C
#define OC   32
#define HEADS 4
#define NEG_SLOPE 0.2f
#define SCAN_BLK 256

// ---------------- device scratch (static: no allocations allowed) ----------
__device__ int   g_is64;
__device__ int   g_esrc[ETOT];          // CSR: src ids grouped by dst
__device__ int   g_deg[NN];             // in-degree per node
__device__ int   g_tmp[NN];             // block-local exclusive scan
__device__ int   g_part[1024];          // per-block partial sums
__device__ int   g_rowptr[NN];          // CSR row starts
__device__ int   g_cursor[NN];          // scatter cursors
__device__ float g_h  [NN * HC];        // projected features [N,128]
__device__ float g_as [NN * HEADS];     // per-node src logits
__device__ float g_ad [NN * HEADS];     // per-node dst logits

// ---------------- init: zero degree histogram + detect edge dtype ----------
__global__ void k_init(const void* ei, int n) {
    int i = blockIdx.x * blockDim.x + threadIdx.x;
    if (i < n) g_deg[i] = 0;
    if (blockIdx.x == 0 && threadIdx.x == 0) {
        const long long* p = (const long long*)ei;
        int ok = 0;
        #pragma unroll 1
        for (int q = 0; q < 64; ++q) {
            long long v = p[q];
            if (v >= 0 && v < (long long)NN) ok++;
        }
        g_is64 = (ok == 64) ? 1 : 0;
    }
}

// ---------------- histogram in-degrees (reads dst half of edge_index) ------
__global__ void k_prep(const void* ei, int e, int n) {
    int i = blockIdx.x * blockDim.x + threadIdx.x;
    int tot = e + n;
    if (i >= tot) return;
    int d;
    if (i < e) {
        if (g_is64) d = (int)((const long long*)ei)[e + i];
        else        d = ((const int*)ei)[e + i];
    } else {
        d = i - e;     // self loop
    }
    atomicAdd(&g_deg[d], 1);
}

// ---------------- exact exclusive scan of g_deg -> g_rowptr ----------------
__global__ void k_scan1(int n) {
    __shared__ int sm[SCAN_BLK];
    int t = threadIdx.x;
    int i = blockIdx.x * SCAN_BLK + t;
    int v = (i < n) ? g_deg[i] : 0;
    sm[t] = v;
    __syncthreads();
    #pragma unroll
    for (int off = 1; off < SCAN_BLK; off <<= 1) {
        int u = (t >= off) ? sm[t - off] : 0;
        __syncthreads();
        sm[t] += u;
        __syncthreads();
    }
    if (i < n) g_tmp[i] = sm[t] - v;            // exclusive
    if (t == SCAN_BLK - 1) g_part[blockIdx.x] = sm[t];
}

__global__ void k_scan2(int nb) {
    __shared__ int sm[1024];
    int t = threadIdx.x;
    int v = (t < nb) ? g_part[t] : 0;
    sm[t] = v;
    __syncthreads();
    #pragma unroll
    for (int off = 1; off < 1024; off <<= 1) {
        int u = (t >= off) ? sm[t - off] : 0;
        __syncthreads();
        sm[t] += u;
        __syncthreads();
    }
    if (t < nb) g_part[t] = sm[t] - v;          // exclusive
}

__global__ void k_scan3(int n) {
    int i = blockIdx.x * blockDim.x + threadIdx.x;
    if (i >= n) return;
    int r = g_tmp[i] + g_part[i / SCAN_BLK];
    g_rowptr[i] = r;
    g_cursor[i] = r;
}

// ---------------- fused GEMM (+logits) || CSR scatter -----------------------
// gemm blocks: 256 thr, 64 rows, W^T + x tile in dyn smem.
// scatter blocks: grid-stride over edges, atomic cursor scatter into g_esrc.
// role interleaved: bid%4==3 -> scatter, else gemm (gid = (bid/4)*3 + bid%4)
__global__ void k_gemm_scatter(const float* __restrict__ x, const float* __restrict__ W,
                               const float* __restrict__ att_s, const float* __restrict__ att_d,
                               const void* ei, int n, int e,
                               int nb_gemm, int nb_scat) {
    int bid = blockIdx.x;
    int tid = threadIdx.x;

    if ((bid & 3) == 3) {
        // ---------------- scatter role ----------------
        int sid = bid >> 2;
        if (sid >= nb_scat) return;
        int etot = e + n;
        int stride = nb_scat * 256;
        int is64 = g_is64;
        for (int i = sid * 256 + tid; i < etot; i += stride) {
            int s, d;
            if (i < e) {
                if (is64) {
                    const long long* p = (const long long*)ei;
                    s = (int)p[i];
                    d = (int)p[e + i];
                } else {
                    const int* p = (const int*)ei;
                    s = p[i];
                    d = p[e + i];
                }
            } else {
                s = d = i - e;
            }
            int pos = atomicAdd(&g_cursor[d], 1);
            g_esrc[pos] = s;
        }
        return;
    }

    // ---------------- gemm role ----------------
    int gid = (bid >> 2) * 3 + (bid & 3);
    if (gid >= nb_gemm) return;

    extern __shared__ float smx[];
    float* Ws = smx;                 // [128][132]  Ws[k*132 + j] = W[j][k]
    float* xs = smx + 128 * 132;     // [64][128]

    for (int idx = tid; idx < HC * INC; idx += 256) {
        int j = idx >> 7, k = idx & 127;
        Ws[k * 132 + j] = W[idx];
    }
    int row0 = gid * 64;
    for (int idx = tid; idx < 64 * INC; idx += 256) {
        int r = idx >> 7;
        xs[idx] = (row0 + r < n) ? x[(size_t)row0 * INC + idx] : 0.0f;
    }
    __syncthreads();

    int tx = tid & 31;   // 4-col group
    int ty = tid >> 5;   // 8-row group
    float acc[8][4];
    #pragma unroll
    for (int r = 0; r < 8; ++r)
        #pragma unroll
        for (int c = 0; c < 4; ++c) acc[r][c] = 0.0f;

    #pragma unroll 4
    for (int k = 0; k < 128; ++k) {
        float4 wv = *(const float4*)&Ws[k * 132 + tx * 4];
        #pragma unroll
        for (int r = 0; r < 8; ++r) {
            float xv = xs[(ty * 8 + r) * 128 + k];
            acc[r][0] = fmaf(xv, wv.x, acc[r][0]);
            acc[r][1] = fmaf(xv, wv.y, acc[r][1]);
            acc[r][2] = fmaf(xv, wv.z, acc[r][2]);
            acc[r][3] = fmaf(xv, wv.w, acc[r][3]);
        }
    }

    #pragma unroll
    for (int r = 0; r < 8; ++r) {
        int row = row0 + ty * 8 + r;
        if (row < n)
            *(float4*)&g_h[(size_t)row * HC + tx * 4] =
                make_float4(acc[r][0], acc[r][1], acc[r][2], acc[r][3]);
    }

    // fused attention logits
    float4 asv = *(const float4*)&att_s[tx * 4];
    float4 adv = *(const float4*)&att_d[tx * 4];
    int head = tx >> 3;
    #pragma unroll
    for (int r = 0; r < 8; ++r) {
        float ps = acc[r][0] * asv.x + acc[r][1] * asv.y + acc[r][2] * asv.z + acc[r][3] * asv.w;
        float pd = acc[r][0] * adv.x + acc[r][1] * adv.y + acc[r][2] * adv.z + acc[r][3] * adv.w;
        #pragma unroll
        for (int o = 4; o > 0; o >>= 1) {
            ps += __shfl_xor_sync(0xffffffffu, ps, o);
            pd += __shfl_xor_sync(0xffffffffu, pd, o);
        }
        int row = row0 + ty * 8 + r;
        if ((tx & 7) == 0 && row < n) {
            g_as[row * HEADS + head] = ps;
            g_ad[row * HEADS + head] = pd;
        }
    }
}

// ---------------- fused gather(softmax+aggregate) + final linear + ELU -----
// 512 threads = 16 warps = 16 nodes per block.
__global__ void k_gather_final(const float* __restrict__ bias,
                               const float* __restrict__ Wl,
                               const float* __restrict__ bl,
                               float* __restrict__ out, int n) {
    __shared__ float Wt[128 * 32];    // Wt[k*32+oc] = Wl[oc*128+k]
    __shared__ float xr[16][128];     // per-warp gathered row (+bias)
    int tid  = threadIdx.x;
    int warp = tid >> 5;
    int lane = tid & 31;
    int node = blockIdx.x * 16 + warp;
    bool valid = node < n;

    for (int idx = tid; idx < OC * HC; idx += 512) {
        int oc = idx >> 7, k = idx & 127;
        Wt[k * 32 + oc] = Wl[idx];
    }

    if (valid) {
        int start = g_rowptr[node];
        int deg   = g_deg[node];
        int hh    = lane >> 3;
        float adv = g_ad[node * HEADS + hh];
        const int* es = &g_esrc[start];

        float sum = 0.0f;
        float ax = 0.f, ay = 0.f, az = 0.f, aw = 0.f;
        int j = 0;
        for (; j + 4 <= deg; j += 4) {
            int s0 = __ldg(es + j), s1 = __ldg(es + j + 1);
            int s2 = __ldg(es + j + 2), s3 = __ldg(es + j + 3);
            float a0 = g_as[s0 * HEADS + hh];
            float a1 = g_as[s1 * HEADS + hh];
            float a2 = g_as[s2 * HEADS + hh];
            float a3 = g_as[s3 * HEADS + hh];
            float4 h0 = *(const float4*)&g_h[(size_t)s0 * HC + lane * 4];
            float4 h1 = *(const float4*)&g_h[(size_t)s1 * HC + lane * 4];
            float4 h2 = *(const float4*)&g_h[(size_t)s2 * HC + lane * 4];
            float4 h3 = *(const float4*)&g_h[(size_t)s3 * HC + lane * 4];
            float e0 = a0 + adv; e0 = e0 > 0.f ? e0 : NEG_SLOPE * e0;
            float e1 = a1 + adv; e1 = e1 > 0.f ? e1 : NEG_SLOPE * e1;
            float e2 = a2 + adv; e2 = e2 > 0.f ? e2 : NEG_SLOPE * e2;
            float e3 = a3 + adv; e3 = e3 > 0.f ? e3 : NEG_SLOPE * e3;
            float w0 = __expf(e0), w1 = __expf(e1), w2 = __expf(e2), w3 = __expf(e3);
            sum += (w0 + w1) + (w2 + w3);
            ax = fmaf(w0, h0.x, fmaf(w1, h1.x, fmaf(w2, h2.x, fmaf(w3, h3.x, ax))));
            ay = fmaf(w0, h0.y, fmaf(w1, h1.y, fmaf(w2, h2.y, fmaf(w3, h3.y, ay))));
            az = fmaf(w0, h0.z, fmaf(w1, h1.z, fmaf(w2, h2.z, fmaf(w3, h3.z, az))));
            aw = fmaf(w0, h0.w, fmaf(w1, h1.w, fmaf(w2, h2.w, fmaf(w3, h3.w, aw))));
        }
        for (; j < deg; ++j) {
            int s0 = __ldg(es + j);
            float a0 = g_as[s0 * HEADS + hh];
            float4 h0 = *(const float4*)&g_h[(size_t)s0 * HC + lane * 4];
            float e0 = a0 + adv; e0 = e0 > 0.f ? e0 : NEG_SLOPE * e0;
            float w0 = __expf(e0);
            sum += w0;
            ax = fmaf(w0, h0.x, ax);
            ay = fmaf(w0, h0.y, ay);
            az = fmaf(w0, h0.z, az);
            aw = fmaf(w0, h0.w, aw);
        }
        float inv = 1.0f / sum;
        float4 bv = *(const float4*)&bias[lane * 4];
        xr[warp][lane * 4 + 0] = fmaf(ax, inv, bv.x);
        xr[warp][lane * 4 + 1] = fmaf(ay, inv, bv.y);
        xr[warp][lane * 4 + 2] = fmaf(az, inv, bv.z);
        xr[warp][lane * 4 + 3] = fmaf(aw, inv, bv.w);
    }
    __syncthreads();
    if (!valid) return;

    // final linear: lane == oc
    int oc = lane;
    float accv = 0.0f;
    const float* row = xr[warp];
    #pragma unroll 8
    for (int k = 0; k < 128; ++k)
        accv = fmaf(row[k], Wt[k * 32 + oc], accv);
    accv += __ldg(&bl[oc]);
    out[(size_t)node * OC + oc] = accv > 0.0f ? accv : (__expf(accv) - 1.0f);
}

// ---------------- launch -----------------------------------------------------
extern "C" void kernel_launch(void* const* d_in, const int* in_sizes, int n_in,
                              void* d_out, int out_size) {
    const float* x     = (const float*)d_in[0];
    const void*  ei    = d_in[1];
    const float* W     = (const float*)d_in[2];
    const float* att_s = (const float*)d_in[3];
    const float* att_d = (const float*)d_in[4];
    const float* bias  = (const float*)d_in[5];
    const float* Wl    = (const float*)d_in[6];
    const float* bl    = (const float*)d_in[7];
    float* out = (float*)d_out;

    int n = in_sizes[0] / INC;
    int e = in_sizes[1] / 2;
    int etot = e + n;
    int nscan = (n + SCAN_BLK - 1) / SCAN_BLK;

    int nb_gemm = (n + 63) / 64;
    int nb_scat = (nb_gemm + 2) / 3;
    int nb_fused = 4 * nb_scat + ((nb_gemm % 3) ? 0 : 0);
    // grid must cover all gemm gids: gid = (bid/4)*3 + bid%4 < nb_gemm
    // with bid < 4*nb_scat this covers (nb_scat)*3 >= nb_gemm  ✓
    nb_fused = 4 * nb_scat;

    static int smem_set = 0;
    if (!smem_set) {
        cudaFuncSetAttribute(k_gemm_scatter, cudaFuncAttributeMaxDynamicSharedMemorySize, 110 * 1024);
        smem_set = 1;
    }
    size_t gemm_smem = (size_t)(128 * 132 + 64 * 128) * sizeof(float);

    k_init<<<(n + 255) / 256, 256>>>(ei, n);
    k_prep<<<(etot + 255) / 256, 256>>>(ei, e, n);
    k_scan1<<<nscan, SCAN_BLK>>>(n);
    k_scan2<<<1, 1024>>>(nscan);
    k_scan3<<<(n + 255) / 256, 256>>>(n);
    k_gemm_scatter<<<nb_fused, 256, gemm_smem>>>(x, W, att_s, att_d, ei, n, e, nb_gemm, nb_scat);
    k_gather_final<<<(n + 15) / 16, 512>>>(bias, Wl, bl, out, n);
}

// round 4
// speedup vs baseline: 2.8308x; 1.0509x over previous
#include <cuda_runtime.h>
#include <math.h>

#define NN   100000
#define EE   1600000
#define ETOT (EE + NN)
#define INC  128
#define HC   128     // HEADS*OUT_C
#define OC   32
#define HEADS 4
#define NEG_SLOPE 0.2f
#define SCAN_BLK 256
#define XS_STRIDE 68   // transposed x tile stride: 16B-aligned, modest write conflicts

typedef unsigned long long u64;

// ---------------- device scratch (static: no allocations allowed) ----------
__device__ int   g_is64;
__device__ int   g_esrc[ETOT];          // CSR: src ids grouped by dst
__device__ int   g_deg[NN];             // in-degree per node
__device__ int   g_tmp[NN];             // block-local exclusive scan
__device__ int   g_part[1024];          // per-block partial sums
__device__ int   g_rowptr[NN];          // CSR row starts
__device__ int   g_cursor[NN];          // scatter cursors
__device__ float g_h  [NN * HC];        // projected features [N,128]
__device__ float g_as [NN * HEADS];     // per-node src logits
__device__ float g_ad [NN * HEADS];     // per-node dst logits

// ---------------- packed f32x2 helpers --------------------------------------
__device__ __forceinline__ u64 pk2(float a, float b) {
    u64 r; asm("mov.b64 %0, {%1, %2};" : "=l"(r) : "f"(a), "f"(b)); return r;
}
__device__ __forceinline__ void fma2(u64& d, u64 a, u64 b) {
    asm("fma.rn.f32x2 %0, %1, %2, %0;" : "+l"(d) : "l"(a), "l"(b));
}
__device__ __forceinline__ float2 up2(u64 v) {
    float2 r; asm("mov.b64 {%0, %1}, %2;" : "=f"(r.x), "=f"(r.y) : "l"(v)); return r;
}

// ---------------- dtype detection (int64 vs int32 edge_index) --------------
__global__ void k_detect(const void* ei) {
    if (blockIdx.x == 0 && threadIdx.x == 0) {
        const long long* p = (const long long*)ei;
        int ok = 0;
        #pragma unroll 1
        for (int q = 0; q < 64; ++q) {
            long long v = p[q];
            if (v >= 0 && v < (long long)NN) ok++;
        }
        g_is64 = (ok == 64) ? 1 : 0;
    }
}

// ---------------- histogram in-degrees (reads dst half of edge_index) ------
__global__ void k_prep(const void* ei, int e, int n) {
    int i = blockIdx.x * blockDim.x + threadIdx.x;
    int tot = e + n;
    if (i >= tot) return;
    int d;
    if (i < e) {
        if (g_is64) d = (int)((const long long*)ei)[e + i];
        else        d = ((const int*)ei)[e + i];
    } else {
        d = i - e;     // self loop
    }
    atomicAdd(&g_deg[d], 1);
}

// ---------------- exact exclusive scan of g_deg -> g_rowptr ----------------
__global__ void k_scan1(int n) {
    __shared__ int sm[SCAN_BLK];
    int t = threadIdx.x;
    int i = blockIdx.x * SCAN_BLK + t;
    int v = (i < n) ? g_deg[i] : 0;
    sm[t] = v;
    __syncthreads();
    #pragma unroll
    for (int off = 1; off < SCAN_BLK; off <<= 1) {
        int u = (t >= off) ? sm[t - off] : 0;
        __syncthreads();
        sm[t] += u;
        __syncthreads();
    }
    if (i < n) g_tmp[i] = sm[t] - v;            // exclusive
    if (t == SCAN_BLK - 1) g_part[blockIdx.x] = sm[t];
}

__global__ void k_scan2(int nb) {
    __shared__ int sm[1024];
    int t = threadIdx.x;
    int v = (t < nb) ? g_part[t] : 0;
    sm[t] = v;
    __syncthreads();
    #pragma unroll
    for (int off = 1; off < 1024; off <<= 1) {
        int u = (t >= off) ? sm[t - off] : 0;
        __syncthreads();
        sm[t] += u;
        __syncthreads();
    }
    if (t < nb) g_part[t] = sm[t] - v;          // exclusive
}

__global__ void k_scan3(int n) {
    int i = blockIdx.x * blockDim.x + threadIdx.x;
    if (i >= n) return;
    int r = g_tmp[i] + g_part[i / SCAN_BLK];
    g_rowptr[i] = r;
    g_cursor[i] = r;
}

// ---------------- fused GEMM (+logits) || CSR scatter -----------------------
// gemm blocks: 256 thr, 64 rows; packed f32x2 math (FFMA2, 2x fp32 rate).
// scatter blocks: grid-stride over edges, atomic cursor scatter into g_esrc.
__global__ void k_gemm_scatter(const float* __restrict__ x, const float* __restrict__ W,
                               const float* __restrict__ att_s, const float* __restrict__ att_d,
                               const void* ei, int n, int e,
                               int nb_gemm, int nb_scat) {
    int bid = blockIdx.x;
    int tid = threadIdx.x;

    if ((bid & 3) == 3) {
        // ---------------- scatter role ----------------
        int sid = bid >> 2;
        if (sid >= nb_scat) return;
        int etot = e + n;
        int stride = nb_scat * 256;
        int is64 = g_is64;
        for (int i = sid * 256 + tid; i < etot; i += stride) {
            int s, d;
            if (i < e) {
                if (is64) {
                    const long long* p = (const long long*)ei;
                    s = (int)p[i];
                    d = (int)p[e + i];
                } else {
                    const int* p = (const int*)ei;
                    s = p[i];
                    d = p[e + i];
                }
            } else {
                s = d = i - e;
            }
            int pos = atomicAdd(&g_cursor[d], 1);
            g_esrc[pos] = s;
        }
        return;
    }

    // ---------------- gemm role ----------------
    int gid = (bid >> 2) * 3 + (bid & 3);
    if (gid >= nb_gemm) return;

    extern __shared__ float smx[];
    float* Ws = smx;                        // [128][132]  Ws[k*132 + j] = W[j][k]
    float* xs = smx + 128 * 132;            // transposed [128][XS_STRIDE]: xs[k*68 + r]

    for (int idx = tid; idx < HC * INC; idx += 256) {
        int j = idx >> 7, k = idx & 127;
        Ws[k * 132 + j] = W[idx];
    }
    int row0 = gid * 64;
    for (int idx = tid; idx < 64 * INC; idx += 256) {
        int r = idx >> 7;        // row within tile
        int k = idx & 127;       // input channel
        float v = (row0 + r < n) ? x[(size_t)row0 * INC + idx] : 0.0f;
        xs[k * XS_STRIDE + r] = v;
    }
    __syncthreads();

    int tx = tid & 31;   // 4-col group (cols tx*4 .. tx*4+3)
    int ty = tid >> 5;   // 8-row group (rows ty*8 .. ty*8+7)

    u64 accp[4][4];      // [row-pair][col] ; pair = rows (2rp, 2rp+1)
    #pragma unroll
    for (int rp = 0; rp < 4; ++rp)
        #pragma unroll
        for (int c = 0; c < 4; ++c) accp[rp][c] = pk2(0.0f, 0.0f);

    const float* xrow = &xs[ty * 8];
    #pragma unroll 4
    for (int k = 0; k < 128; ++k) {
        float4 wv = *(const float4*)&Ws[k * 132 + tx * 4];
        u64 wd0 = pk2(wv.x, wv.x);
        u64 wd1 = pk2(wv.y, wv.y);
        u64 wd2 = pk2(wv.z, wv.z);
        u64 wd3 = pk2(wv.w, wv.w);
        ulonglong2 xpa = *(const ulonglong2*)&xrow[k * XS_STRIDE];      // rows 0-3
        ulonglong2 xpb = *(const ulonglong2*)&xrow[k * XS_STRIDE + 4];  // rows 4-7
        fma2(accp[0][0], xpa.x, wd0); fma2(accp[0][1], xpa.x, wd1);
        fma2(accp[0][2], xpa.x, wd2); fma2(accp[0][3], xpa.x, wd3);
        fma2(accp[1][0], xpa.y, wd0); fma2(accp[1][1], xpa.y, wd1);
        fma2(accp[1][2], xpa.y, wd2); fma2(accp[1][3], xpa.y, wd3);
        fma2(accp[2][0], xpb.x, wd0); fma2(accp[2][1], xpb.x, wd1);
        fma2(accp[2][2], xpb.x, wd2); fma2(accp[2][3], xpb.x, wd3);
        fma2(accp[3][0], xpb.y, wd0); fma2(accp[3][1], xpb.y, wd1);
        fma2(accp[3][2], xpb.y, wd2); fma2(accp[3][3], xpb.y, wd3);
    }

    float4 asv = *(const float4*)&att_s[tx * 4];
    float4 adv = *(const float4*)&att_d[tx * 4];
    int head = tx >> 3;

    #pragma unroll
    for (int rp = 0; rp < 4; ++rp) {
        float2 p0 = up2(accp[rp][0]);
        float2 p1 = up2(accp[rp][1]);
        float2 p2 = up2(accp[rp][2]);
        float2 p3 = up2(accp[rp][3]);
        int row_e = row0 + ty * 8 + 2 * rp;
        int row_o = row_e + 1;
        if (row_e < n)
            *(float4*)&g_h[(size_t)row_e * HC + tx * 4] = make_float4(p0.x, p1.x, p2.x, p3.x);
        if (row_o < n)
            *(float4*)&g_h[(size_t)row_o * HC + tx * 4] = make_float4(p0.y, p1.y, p2.y, p3.y);

        // logits for both rows of the pair
        float pse = p0.x * asv.x + p1.x * asv.y + p2.x * asv.z + p3.x * asv.w;
        float pde = p0.x * adv.x + p1.x * adv.y + p2.x * adv.z + p3.x * adv.w;
        float pso = p0.y * asv.x + p1.y * asv.y + p2.y * asv.z + p3.y * asv.w;
        float pdo = p0.y * adv.x + p1.y * adv.y + p2.y * adv.z + p3.y * adv.w;
        #pragma unroll
        for (int o = 4; o > 0; o >>= 1) {
            pse += __shfl_xor_sync(0xffffffffu, pse, o);
            pde += __shfl_xor_sync(0xffffffffu, pde, o);
            pso += __shfl_xor_sync(0xffffffffu, pso, o);
            pdo += __shfl_xor_sync(0xffffffffu, pdo, o);
        }
        if ((tx & 7) == 0) {
            if (row_e < n) { g_as[row_e * HEADS + head] = pse; g_ad[row_e * HEADS + head] = pde; }
            if (row_o < n) { g_as[row_o * HEADS + head] = pso; g_ad[row_o * HEADS + head] = pdo; }
        }
    }
}

// ---------------- fused gather(softmax+aggregate) + final linear + ELU -----
// 512 threads = 16 warps = 16 nodes per block.
__global__ void k_gather_final(const float* __restrict__ bias,
                               const float* __restrict__ Wl,
                               const float* __restrict__ bl,
                               float* __restrict__ out, int n) {
    __shared__ float Wt[128 * 32];    // Wt[k*32+oc] = Wl[oc*128+k]
    __shared__ float xr[16][128];     // per-warp gathered row (+bias)
    int tid  = threadIdx.x;
    int warp = tid >> 5;
    int lane = tid & 31;
    int node = blockIdx.x * 16 + warp;
    bool valid = node < n;

    for (int idx = tid; idx < OC * HC; idx += 512) {
        int oc = idx >> 7, k = idx & 127;
        Wt[k * 32 + oc] = Wl[idx];
    }

    if (valid) {
        int start = g_rowptr[node];
        int deg   = g_deg[node];
        int hh    = lane >> 3;
        float adv = g_ad[node * HEADS + hh];
        const int* es = &g_esrc[start];

        float sum = 0.0f;
        float ax = 0.f, ay = 0.f, az = 0.f, aw = 0.f;
        int j = 0;
        for (; j + 4 <= deg; j += 4) {
            int s0 = __ldg(es + j), s1 = __ldg(es + j + 1);
            int s2 = __ldg(es + j + 2), s3 = __ldg(es + j + 3);
            float a0 = g_as[s0 * HEADS + hh];
            float a1 = g_as[s1 * HEADS + hh];
            float a2 = g_as[s2 * HEADS + hh];
            float a3 = g_as[s3 * HEADS + hh];
            float4 h0 = *(const float4*)&g_h[(size_t)s0 * HC + lane * 4];
            float4 h1 = *(const float4*)&g_h[(size_t)s1 * HC + lane * 4];
            float4 h2 = *(const float4*)&g_h[(size_t)s2 * HC + lane * 4];
            float4 h3 = *(const float4*)&g_h[(size_t)s3 * HC + lane * 4];
            float e0 = a0 + adv; e0 = e0 > 0.f ? e0 : NEG_SLOPE * e0;
            float e1 = a1 + adv; e1 = e1 > 0.f ? e1 : NEG_SLOPE * e1;
            float e2 = a2 + adv; e2 = e2 > 0.f ? e2 : NEG_SLOPE * e2;
            float e3 = a3 + adv; e3 = e3 > 0.f ? e3 : NEG_SLOPE * e3;
            float w0 = __expf(e0), w1 = __expf(e1), w2 = __expf(e2), w3 = __expf(e3);
            sum += (w0 + w1) + (w2 + w3);
            ax = fmaf(w0, h0.x, fmaf(w1, h1.x, fmaf(w2, h2.x, fmaf(w3, h3.x, ax))));
            ay = fmaf(w0, h0.y, fmaf(w1, h1.y, fmaf(w2, h2.y, fmaf(w3, h3.y, ay))));
            az = fmaf(w0, h0.z, fmaf(w1, h1.z, fmaf(w2, h2.z, fmaf(w3, h3.z, az))));
            aw = fmaf(w0, h0.w, fmaf(w1, h1.w, fmaf(w2, h2.w, fmaf(w3, h3.w, aw))));
        }
        for (; j < deg; ++j) {
            int s0 = __ldg(es + j);
            float a0 = g_as[s0 * HEADS + hh];
            float4 h0 = *(const float4*)&g_h[(size_t)s0 * HC + lane * 4];
            float e0 = a0 + adv; e0 = e0 > 0.f ? e0 : NEG_SLOPE * e0;
            float w0 = __expf(e0);
            sum += w0;
            ax = fmaf(w0, h0.x, ax);
            ay = fmaf(w0, h0.y, ay);
            az = fmaf(w0, h0.z, az);
            aw = fmaf(w0, h0.w, aw);
        }
        float inv = 1.0f / sum;
        float4 bv = *(const float4*)&bias[lane * 4];
        xr[warp][lane * 4 + 0] = fmaf(ax, inv, bv.x);
        xr[warp][lane * 4 + 1] = fmaf(ay, inv, bv.y);
        xr[warp][lane * 4 + 2] = fmaf(az, inv, bv.z);
        xr[warp][lane * 4 + 3] = fmaf(aw, inv, bv.w);
    }
    __syncthreads();
    if (!valid) return;

    // final linear: lane == oc
    int oc = lane;
    float accv = 0.0f;
    const float* row = xr[warp];
    #pragma unroll 8
    for (int k = 0; k < 128; ++k)
        accv = fmaf(row[k], Wt[k * 32 + oc], accv);
    accv += __ldg(&bl[oc]);
    out[(size_t)node * OC + oc] = accv > 0.0f ? accv : (__expf(accv) - 1.0f);
}

// ---------------- launch -----------------------------------------------------
extern "C" void kernel_launch(void* const* d_in, const int* in_sizes, int n_in,
                              void* d_out, int out_size) {
    const float* x     = (const float*)d_in[0];
    const void*  ei    = d_in[1];
    const float* W     = (const float*)d_in[2];
    const float* att_s = (const float*)d_in[3];
    const float* att_d = (const float*)d_in[4];
    const float* bias  = (const float*)d_in[5];
    const float* Wl    = (const float*)d_in[6];
    const float* bl    = (const float*)d_in[7];
    float* out = (float*)d_out;

    int n = in_sizes[0] / INC;
    int e = in_sizes[1] / 2;
    int etot = e + n;
    int nscan = (n + SCAN_BLK - 1) / SCAN_BLK;

    int nb_gemm = (n + 63) / 64;
    int nb_scat = (nb_gemm + 2) / 3;
    int nb_fused = 4 * nb_scat;

    static void* deg_ptr = nullptr;
    static int smem_set = 0;
    if (!smem_set) {
        cudaFuncSetAttribute(k_gemm_scatter, cudaFuncAttributeMaxDynamicSharedMemorySize, 110 * 1024);
        cudaGetSymbolAddress(&deg_ptr, g_deg);
        smem_set = 1;
    }
    size_t gemm_smem = (size_t)(128 * 132 + 128 * XS_STRIDE) * sizeof(float);

    k_detect<<<1, 32>>>(ei);
    cudaMemsetAsync(deg_ptr, 0, (size_t)n * sizeof(int));
    k_prep<<<(etot + 255) / 256, 256>>>(ei, e, n);
    k_scan1<<<nscan, SCAN_BLK>>>(n);
    k_scan2<<<1, 1024>>>(nscan);
    k_scan3<<<(n + 255) / 256, 256>>>(n);
    k_gemm_scatter<<<nb_fused, 256, gemm_smem>>>(x, W, att_s, att_d, ei, n, e, nb_gemm, nb_scat);
    k_gather_final<<<(n + 15) / 16, 512>>>(bias, Wl, bl, out, n);
}

// round 5
// speedup vs baseline: 2.9365x; 1.0373x over previous
#include <cuda_runtime.h>
#include <math.h>

#define NN   100000
#define EE   1600000
#define ETOT (EE + NN)
#define INC  128
#define HC   128     // HEADS*OUT_C
#define OC   32
#define HEADS 4
#define NEG_SLOPE 0.2f
#define SCAN_BLK 256
#define XS_STRIDE 68

typedef unsigned long long u64;

// ---------------- device scratch (static: no allocations allowed) ----------
__device__ int   g_esrc[ETOT];          // CSR: src ids grouped by dst
__device__ int   g_deg[NN];             // in-degree per node
__device__ int   g_tmp[NN];             // block-local exclusive scan
__device__ int   g_part[1024];          // per-block partial sums
__device__ int   g_rowptr[NN];          // CSR row starts
__device__ int   g_cursor[NN];          // scatter cursors
__device__ float g_h  [NN * HC];        // projected features [N,128]
__device__ float g_as [NN * HEADS];     // per-node src logits
__device__ float g_ad [NN * HEADS];     // per-node dst logits

// ---------------- packed f32x2 helpers --------------------------------------
__device__ __forceinline__ u64 pk2(float a, float b) {
    u64 r; asm("mov.b64 %0, {%1, %2};" : "=l"(r) : "f"(a), "f"(b)); return r;
}
__device__ __forceinline__ void fma2(u64& d, u64 a, u64 b) {
    asm("fma.rn.f32x2 %0, %1, %2, %0;" : "+l"(d) : "l"(a), "l"(b));
}
__device__ __forceinline__ float2 up2(u64 v) {
    float2 r; asm("mov.b64 {%0, %1}, %2;" : "=f"(r.x), "=f"(r.y) : "l"(v)); return r;
}

// per-call dtype detection: reads first 64 entries as int64; all-valid => i64
__device__ __forceinline__ int detect64(const void* ei) {
    const long long* p = (const long long*)ei;
    int ok = 1;
    #pragma unroll 1
    for (int q = 0; q < 64; ++q) {
        long long v = p[q];
        if (!(v >= 0 && v < (long long)NN)) { ok = 0; break; }
    }
    return ok;
}

// ---------------- histogram in-degrees (reads dst half of edge_index) ------
__global__ void k_prep(const void* ei, int e, int n) {
    int is64 = detect64(ei);
    int i = blockIdx.x * blockDim.x + threadIdx.x;
    int tot = e + n;
    if (i >= tot) return;
    int d;
    if (i < e) {
        if (is64) d = (int)((const long long*)ei)[e + i];
        else      d = ((const int*)ei)[e + i];
    } else {
        d = i - e;     // self loop
    }
    atomicAdd(&g_deg[d], 1);
}

// ---------------- scan stage 1: per-block exclusive scan --------------------
__global__ void k_scan1(int n) {
    __shared__ int sm[SCAN_BLK];
    int t = threadIdx.x;
    int i = blockIdx.x * SCAN_BLK + t;
    int v = (i < n) ? g_deg[i] : 0;
    sm[t] = v;
    __syncthreads();
    #pragma unroll
    for (int off = 1; off < SCAN_BLK; off <<= 1) {
        int u = (t >= off) ? sm[t - off] : 0;
        __syncthreads();
        sm[t] += u;
        __syncthreads();
    }
    if (i < n) g_tmp[i] = sm[t] - v;            // exclusive
    if (t == SCAN_BLK - 1) g_part[blockIdx.x] = sm[t];
}

// ---------------- scan stage 2+3: block b sums g_part[0..b) directly --------
__global__ void k_scan23(int n) {
    __shared__ int sm[SCAN_BLK];
    int b = blockIdx.x, t = threadIdx.x;
    int acc = 0;
    for (int j = t; j < b; j += SCAN_BLK) acc += g_part[j];
    sm[t] = acc;
    __syncthreads();
    #pragma unroll
    for (int off = SCAN_BLK / 2; off > 0; off >>= 1) {
        if (t < off) sm[t] += sm[t + off];
        __syncthreads();
    }
    int base = sm[0];
    int i = b * SCAN_BLK + t;
    if (i < n) {
        int r = g_tmp[i] + base;
        g_rowptr[i] = r;
        g_cursor[i] = r;
    }
}

// ---------------- fused GEMM (+logits) || CSR scatter -----------------------
__global__ void k_gemm_scatter(const float* __restrict__ x, const float* __restrict__ W,
                               const float* __restrict__ att_s, const float* __restrict__ att_d,
                               const void* ei, int n, int e,
                               int nb_gemm, int nb_scat) {
    int bid = blockIdx.x;
    int tid = threadIdx.x;

    if ((bid & 3) == 3) {
        // ---------------- scatter role ----------------
        int sid = bid >> 2;
        if (sid >= nb_scat) return;
        int is64 = detect64(ei);
        int etot = e + n;
        int stride = nb_scat * 256;
        for (int i = sid * 256 + tid; i < etot; i += stride) {
            int s, d;
            if (i < e) {
                if (is64) {
                    const long long* p = (const long long*)ei;
                    s = (int)p[i];
                    d = (int)p[e + i];
                } else {
                    const int* p = (const int*)ei;
                    s = p[i];
                    d = p[e + i];
                }
            } else {
                s = d = i - e;
            }
            int pos = atomicAdd(&g_cursor[d], 1);
            g_esrc[pos] = s;
        }
        return;
    }

    // ---------------- gemm role ----------------
    int gid = (bid >> 2) * 3 + (bid & 3);
    if (gid >= nb_gemm) return;

    extern __shared__ float smx[];
    float* Ws = smx;                        // [128][132]  Ws[k*132 + j] = W[j][k]
    float* xs = smx + 128 * 132;            // transposed [128][XS_STRIDE]

    for (int idx = tid; idx < HC * INC; idx += 256) {
        int j = idx >> 7, k = idx & 127;
        Ws[k * 132 + j] = W[idx];
    }
    int row0 = gid * 64;
    for (int idx = tid; idx < 64 * INC; idx += 256) {
        int r = idx >> 7;
        int k = idx & 127;
        float v = (row0 + r < n) ? x[(size_t)row0 * INC + idx] : 0.0f;
        xs[k * XS_STRIDE + r] = v;
    }
    __syncthreads();

    int tx = tid & 31;
    int ty = tid >> 5;

    u64 accp[4][4];
    #pragma unroll
    for (int rp = 0; rp < 4; ++rp)
        #pragma unroll
        for (int c = 0; c < 4; ++c) accp[rp][c] = pk2(0.0f, 0.0f);

    const float* xrow = &xs[ty * 8];
    #pragma unroll 4
    for (int k = 0; k < 128; ++k) {
        float4 wv = *(const float4*)&Ws[k * 132 + tx * 4];
        u64 wd0 = pk2(wv.x, wv.x);
        u64 wd1 = pk2(wv.y, wv.y);
        u64 wd2 = pk2(wv.z, wv.z);
        u64 wd3 = pk2(wv.w, wv.w);
        ulonglong2 xpa = *(const ulonglong2*)&xrow[k * XS_STRIDE];
        ulonglong2 xpb = *(const ulonglong2*)&xrow[k * XS_STRIDE + 4];
        fma2(accp[0][0], xpa.x, wd0); fma2(accp[0][1], xpa.x, wd1);
        fma2(accp[0][2], xpa.x, wd2); fma2(accp[0][3], xpa.x, wd3);
        fma2(accp[1][0], xpa.y, wd0); fma2(accp[1][1], xpa.y, wd1);
        fma2(accp[1][2], xpa.y, wd2); fma2(accp[1][3], xpa.y, wd3);
        fma2(accp[2][0], xpb.x, wd0); fma2(accp[2][1], xpb.x, wd1);
        fma2(accp[2][2], xpb.x, wd2); fma2(accp[2][3], xpb.x, wd3);
        fma2(accp[3][0], xpb.y, wd0); fma2(accp[3][1], xpb.y, wd1);
        fma2(accp[3][2], xpb.y, wd2); fma2(accp[3][3], xpb.y, wd3);
    }

    float4 asv = *(const float4*)&att_s[tx * 4];
    float4 adv = *(const float4*)&att_d[tx * 4];
    int head = tx >> 3;

    #pragma unroll
    for (int rp = 0; rp < 4; ++rp) {
        float2 p0 = up2(accp[rp][0]);
        float2 p1 = up2(accp[rp][1]);
        float2 p2 = up2(accp[rp][2]);
        float2 p3 = up2(accp[rp][3]);
        int row_e = row0 + ty * 8 + 2 * rp;
        int row_o = row_e + 1;
        if (row_e < n)
            *(float4*)&g_h[(size_t)row_e * HC + tx * 4] = make_float4(p0.x, p1.x, p2.x, p3.x);
        if (row_o < n)
            *(float4*)&g_h[(size_t)row_o * HC + tx * 4] = make_float4(p0.y, p1.y, p2.y, p3.y);

        float pse = p0.x * asv.x + p1.x * asv.y + p2.x * asv.z + p3.x * asv.w;
        float pde = p0.x * adv.x + p1.x * adv.y + p2.x * adv.z + p3.x * adv.w;
        float pso = p0.y * asv.x + p1.y * asv.y + p2.y * asv.z + p3.y * asv.w;
        float pdo = p0.y * adv.x + p1.y * adv.y + p2.y * adv.z + p3.y * adv.w;
        #pragma unroll
        for (int o = 4; o > 0; o >>= 1) {
            pse += __shfl_xor_sync(0xffffffffu, pse, o);
            pde += __shfl_xor_sync(0xffffffffu, pde, o);
            pso += __shfl_xor_sync(0xffffffffu, pso, o);
            pdo += __shfl_xor_sync(0xffffffffu, pdo, o);
        }
        if ((tx & 7) == 0) {
            if (row_e < n) { g_as[row_e * HEADS + head] = pse; g_ad[row_e * HEADS + head] = pde; }
            if (row_o < n) { g_as[row_o * HEADS + head] = pso; g_ad[row_o * HEADS + head] = pdo; }
        }
    }
}

// ---------------- fused gather + final linear; warps retire independently ---
__global__ void k_gather_final(const float* __restrict__ bias,
                               const float* __restrict__ Wl,
                               const float* __restrict__ bl,
                               float* __restrict__ out, int n) {
    __shared__ float Wt[128 * 32];    // Wt[k*32+oc]
    __shared__ float xr[16][128];
    int tid  = threadIdx.x;
    int warp = tid >> 5;
    int lane = tid & 31;
    int node = blockIdx.x * 16 + warp;

    for (int idx = tid; idx < OC * HC; idx += 512) {
        int oc = idx >> 7, k = idx & 127;
        Wt[k * 32 + oc] = Wl[idx];
    }
    __syncthreads();          // only sync: Wt ready
    if (node >= n) return;

    int start = g_rowptr[node];
    int deg   = g_deg[node];
    int hh    = lane >> 3;
    float adv = g_ad[node * HEADS + hh];
    const int* es = &g_esrc[start];

    float sum = 0.0f;
    float ax = 0.f, ay = 0.f, az = 0.f, aw = 0.f;
    int j = 0;
    for (; j + 4 <= deg; j += 4) {
        int s0 = __ldg(es + j), s1 = __ldg(es + j + 1);
        int s2 = __ldg(es + j + 2), s3 = __ldg(es + j + 3);
        float a0 = g_as[s0 * HEADS + hh];
        float a1 = g_as[s1 * HEADS + hh];
        float a2 = g_as[s2 * HEADS + hh];
        float a3 = g_as[s3 * HEADS + hh];
        float4 h0 = *(const float4*)&g_h[(size_t)s0 * HC + lane * 4];
        float4 h1 = *(const float4*)&g_h[(size_t)s1 * HC + lane * 4];
        float4 h2 = *(const float4*)&g_h[(size_t)s2 * HC + lane * 4];
        float4 h3 = *(const float4*)&g_h[(size_t)s3 * HC + lane * 4];
        float e0 = a0 + adv; e0 = e0 > 0.f ? e0 : NEG_SLOPE * e0;
        float e1 = a1 + adv; e1 = e1 > 0.f ? e1 : NEG_SLOPE * e1;
        float e2 = a2 + adv; e2 = e2 > 0.f ? e2 : NEG_SLOPE * e2;
        float e3 = a3 + adv; e3 = e3 > 0.f ? e3 : NEG_SLOPE * e3;
        float w0 = __expf(e0), w1 = __expf(e1), w2 = __expf(e2), w3 = __expf(e3);
        sum += (w0 + w1) + (w2 + w3);
        ax = fmaf(w0, h0.x, fmaf(w1, h1.x, fmaf(w2, h2.x, fmaf(w3, h3.x, ax))));
        ay = fmaf(w0, h0.y, fmaf(w1, h1.y, fmaf(w2, h2.y, fmaf(w3, h3.y, ay))));
        az = fmaf(w0, h0.z, fmaf(w1, h1.z, fmaf(w2, h2.z, fmaf(w3, h3.z, az))));
        aw = fmaf(w0, h0.w, fmaf(w1, h1.w, fmaf(w2, h2.w, fmaf(w3, h3.w, aw))));
    }
    for (; j < deg; ++j) {
        int s0 = __ldg(es + j);
        float a0 = g_as[s0 * HEADS + hh];
        float4 h0 = *(const float4*)&g_h[(size_t)s0 * HC + lane * 4];
        float e0 = a0 + adv; e0 = e0 > 0.f ? e0 : NEG_SLOPE * e0;
        float w0 = __expf(e0);
        sum += w0;
        ax = fmaf(w0, h0.x, ax);
        ay = fmaf(w0, h0.y, ay);
        az = fmaf(w0, h0.z, az);
        aw = fmaf(w0, h0.w, aw);
    }
    float inv = 1.0f / sum;
    float4 bv = *(const float4*)&bias[lane * 4];
    xr[warp][lane * 4 + 0] = fmaf(ax, inv, bv.x);
    xr[warp][lane * 4 + 1] = fmaf(ay, inv, bv.y);
    xr[warp][lane * 4 + 2] = fmaf(az, inv, bv.z);
    xr[warp][lane * 4 + 3] = fmaf(aw, inv, bv.w);
    __syncwarp();             // warp-local: xr row visible to all lanes

    int oc = lane;
    float accv = 0.0f;
    const float* row = xr[warp];
    #pragma unroll 8
    for (int k = 0; k < 128; ++k)
        accv = fmaf(row[k], Wt[k * 32 + oc], accv);
    accv += __ldg(&bl[oc]);
    out[(size_t)node * OC + oc] = accv > 0.0f ? accv : (__expf(accv) - 1.0f);
}

// ---------------- launch -----------------------------------------------------
extern "C" void kernel_launch(void* const* d_in, const int* in_sizes, int n_in,
                              void* d_out, int out_size) {
    const float* x     = (const float*)d_in[0];
    const void*  ei    = d_in[1];
    const float* W     = (const float*)d_in[2];
    const float* att_s = (const float*)d_in[3];
    const float* att_d = (const float*)d_in[4];
    const float* bias  = (const float*)d_in[5];
    const float* Wl    = (const float*)d_in[6];
    const float* bl    = (const float*)d_in[7];
    float* out = (float*)d_out;

    int n = in_sizes[0] / INC;
    int e = in_sizes[1] / 2;
    int etot = e + n;
    int nscan = (n + SCAN_BLK - 1) / SCAN_BLK;

    int nb_gemm = (n + 63) / 64;
    int nb_scat = (nb_gemm + 2) / 3;
    int nb_fused = 4 * nb_scat;

    static void* deg_ptr = nullptr;
    static int smem_set = 0;
    if (!smem_set) {
        cudaFuncSetAttribute(k_gemm_scatter, cudaFuncAttributeMaxDynamicSharedMemorySize, 110 * 1024);
        cudaGetSymbolAddress(&deg_ptr, g_deg);
        smem_set = 1;
    }
    size_t gemm_smem = (size_t)(128 * 132 + 128 * XS_STRIDE) * sizeof(float);

    cudaMemsetAsync(deg_ptr, 0, (size_t)n * sizeof(int));
    k_prep<<<(etot + 255) / 256, 256>>>(ei, e, n);                 // launch 1
    k_scan1<<<nscan, SCAN_BLK>>>(n);                               // launch 2
    k_scan23<<<nscan, SCAN_BLK>>>(n);                              // launch 3
    k_gemm_scatter<<<nb_fused, 256, gemm_smem>>>(x, W, att_s, att_d, ei, n, e, nb_gemm, nb_scat);  // launch 4 (profiled)
    k_gather_final<<<(n + 15) / 16, 512>>>(bias, Wl, bl, out, n);  // launch 5
}